// round 15
// baseline (speedup 1.0000x reference)
#include <cuda_runtime.h>
#include <math.h>
#include <stdint.h>

#define BB    2
#define SS    2048
#define DIMV  2048
#define H     16
#define DK    128
#define DV    128
#define KD    2048
#define VD    2048
#define KCONV 4
#define BS    (BB*SS)   // 4096

// ---------------- scratch (static __device__, no allocs) ----------------
__device__ float    g_qlin[BS*KD];
__device__ float    g_klin[BS*KD];
__device__ float    g_vlin[BS*VD];
__device__ float    g_glin[BS*VD];
__device__ float    g_qn[BS*KD];
__device__ float    g_kn[BS*KD];
__device__ float    g_vc[BS*VD];
__device__ float    g_o[BS*VD];
__device__ float    g_g[BS*H];
__device__ float    g_beta[BS*H];
__device__ uint32_t g_xt[BS*DIMV];        // x in tf32 bits
__device__ uint32_t g_w4[4*KD*DIMV];      // Wq|Wk|Wv|Wg in tf32 bits
__device__ uint32_t g_wot[DIMV*VD];       // Wo in tf32 bits
__device__ uint32_t g_ogt[BS*VD];         // rmsnorm*gate output in tf32 bits

__device__ __forceinline__ uint32_t f2tf32(float x) {
    uint32_t r;
    asm("cvt.rna.tf32.f32 %0, %1;" : "=r"(r) : "f"(x));
    return r;
}

// ---------------- fp32 -> tf32 conversions ----------------
__global__ void cvt_tf32_kernel(const float* __restrict__ in, uint32_t* __restrict__ out)
{
    size_t i = ((size_t)blockIdx.x * 256 + threadIdx.x) * 4;
    float4 v = *(const float4*)(in + i);
    uint4 u;
    u.x = f2tf32(v.x); u.y = f2tf32(v.y); u.z = f2tf32(v.z); u.w = f2tf32(v.w);
    *(uint4*)(out + i) = u;
}

struct CvtPtrs { const float* src[4]; uint32_t* dst[4]; };

__global__ void cvt_w_kernel(CvtPtrs P)
{
    int m = blockIdx.y;
    const float* in  = P.src[m];
    uint32_t*    out = P.dst[m];
    size_t i = ((size_t)blockIdx.x * 256 + threadIdx.x) * 4;
    float4 v = *(const float4*)(in + i);
    uint4 u;
    u.x = f2tf32(v.x); u.y = f2tf32(v.y); u.z = f2tf32(v.z); u.w = f2tf32(v.w);
    *(uint4*)(out + i) = u;
}

// ---------------- TF32 tensor-core GEMM NT, cp.async double-buffered ----
// (round-3 configuration: 256 thr, 8 warps x (64x32), BK=32, 2 stages)
#define SMS 36            // word stride: 36 mod 32 = 4 -> LDS bank = lane perm
#define STAGE_WORDS (128*SMS)

#define MMA_TF32(d, a, b)                                                      \
    asm volatile(                                                              \
        "mma.sync.aligned.m16n8k8.row.col.f32.tf32.tf32.f32 "                  \
        "{%0,%1,%2,%3},{%4,%5,%6,%7},{%8,%9},{%0,%1,%2,%3};"                   \
        : "+f"(d[0]), "+f"(d[1]), "+f"(d[2]), "+f"(d[3])                       \
        : "r"(a[0]), "r"(a[1]), "r"(a[2]), "r"(a[3]), "r"(b[0]), "r"(b[1]))

__device__ __forceinline__ void cpa16(uint32_t saddr, const void* gptr) {
    asm volatile("cp.async.ca.shared.global [%0], [%1], 16;\n" :: "r"(saddr), "l"(gptr));
}

struct GemmPtrs {
    const uint32_t* Bw[4];
    float*          C[4];
};

__global__ __launch_bounds__(256, 2) void mma_gemm_tf32(
    const uint32_t* __restrict__ A, GemmPtrs P, int K, int N)
{
    extern __shared__ uint32_t smem[];
    uint32_t* As = smem;                     // [2][STAGE_WORDS]
    uint32_t* Bs = smem + 2*STAGE_WORDS;     // [2][STAGE_WORDS]

    int buf = blockIdx.x >> 4;
    int nb  = blockIdx.x & 15;
    const uint32_t* Bw = P.Bw[buf];
    float*          C  = P.C[buf];

    int tid   = threadIdx.x;
    int lane  = tid & 31;
    int warp  = tid >> 5;
    int warpM = warp >> 2;
    int warpN = warp & 3;
    int mBase = blockIdx.y * 128;
    int nBase = nb * 128;
    int g = lane >> 2;
    int t = lane & 3;

    uint32_t sA = (uint32_t)__cvta_generic_to_shared(As);
    uint32_t sB = (uint32_t)__cvta_generic_to_shared(Bs);

    float acc[4][4][4];
    #pragma unroll
    for (int i = 0; i < 4; i++)
        #pragma unroll
        for (int j = 0; j < 4; j++)
            #pragma unroll
            for (int r = 0; r < 4; r++) acc[i][j][r] = 0.f;

    #define LOAD_STAGE(stg, kb)                                                 \
        do {                                                                    \
            _Pragma("unroll")                                                   \
            for (int j = 0; j < 4; j++) {                                       \
                int idx = tid + j * 256;                                        \
                int row = idx >> 3;                                             \
                int kc  = (idx & 7) << 2;                                       \
                cpa16(sA + ((stg)*STAGE_WORDS + row*SMS + kc)*4,                \
                      &A[(size_t)(mBase + row)*K + (kb) + kc]);                 \
                cpa16(sB + ((stg)*STAGE_WORDS + row*SMS + kc)*4,                \
                      &Bw[(size_t)(nBase + row)*K + (kb) + kc]);                \
            }                                                                   \
            asm volatile("cp.async.commit_group;\n");                           \
        } while (0)

    LOAD_STAGE(0, 0);
    int NIT = K >> 5;
    for (int it = 0; it < NIT; it++) {
        int cur = it & 1;
        if (it + 1 < NIT) {
            LOAD_STAGE(cur ^ 1, (it + 1) << 5);
            asm volatile("cp.async.wait_group 1;\n");
        } else {
            asm volatile("cp.async.wait_group 0;\n");
        }
        __syncthreads();

        const uint32_t* Ac = As + cur*STAGE_WORDS;
        const uint32_t* Bc = Bs + cur*STAGE_WORDS;
        #pragma unroll
        for (int ks = 0; ks < 4; ks++) {
            int k0 = ks * 8;
            uint32_t af[4][4], bf[4][2];
            #pragma unroll
            for (int mt = 0; mt < 4; mt++) {
                int m = warpM*64 + mt*16;
                af[mt][0] = Ac[(m + g    )*SMS + k0 + t];
                af[mt][1] = Ac[(m + g + 8)*SMS + k0 + t];
                af[mt][2] = Ac[(m + g    )*SMS + k0 + t + 4];
                af[mt][3] = Ac[(m + g + 8)*SMS + k0 + t + 4];
            }
            #pragma unroll
            for (int nt = 0; nt < 4; nt++) {
                int n = warpN*32 + nt*8;
                bf[nt][0] = Bc[(n + g)*SMS + k0 + t];
                bf[nt][1] = Bc[(n + g)*SMS + k0 + t + 4];
            }
            #pragma unroll
            for (int mt = 0; mt < 4; mt++)
                #pragma unroll
                for (int nt = 0; nt < 4; nt++)
                    MMA_TF32(acc[mt][nt], af[mt], bf[nt]);
        }
        __syncthreads();
    }

    #pragma unroll
    for (int mt = 0; mt < 4; mt++) {
        #pragma unroll
        for (int nt = 0; nt < 4; nt++) {
            int row = mBase + warpM*64 + mt*16 + g;
            int col = nBase + warpN*32 + nt*8 + 2*t;
            *(float2*)&C[(size_t)row * N + col] =
                make_float2(acc[mt][nt][0], acc[mt][nt][1]);
            *(float2*)&C[(size_t)(row + 8) * N + col] =
                make_float2(acc[mt][nt][2], acc[mt][nt][3]);
        }
    }
}

// ---------------- a/b projections, 8 rows per block ----------------
__global__ __launch_bounds__(256) void ab_kernel(
    const float* __restrict__ x, const float* __restrict__ Wa,
    const float* __restrict__ Wb, const float* __restrict__ A_log,
    const float* __restrict__ dt_bias)
{
    extern __shared__ float xsh[];   // 8*2048 floats = 64KB
    int row0 = blockIdx.x * 8;
    int tid  = threadIdx.x;
    int lane = tid & 31;
    int warp = tid >> 5;

    #pragma unroll
    for (int j = 0; j < 16; j++) {
        int idx = tid + j*256;          // 0..4095 float4s
        int r   = idx >> 9;             // 512 float4 per row
        int cw  = idx & 511;
        ((float4*)xsh)[idx] =
            ((const float4*)(x + (size_t)(row0 + r)*DIMV))[cw];
    }
    __syncthreads();

    #pragma unroll
    for (int hh = 0; hh < 4; hh++) {
        int hidx = warp*4 + hh;                 // 0..31
        const float* wrow = (hidx < H) ? (Wa + (size_t)hidx*DIMV)
                                       : (Wb + (size_t)(hidx - H)*DIMV);
        float acc[8];
        #pragma unroll
        for (int r = 0; r < 8; r++) acc[r] = 0.f;
        for (int i = lane*4; i < DIMV; i += 128) {
            float4 wv = *(const float4*)&wrow[i];
            #pragma unroll
            for (int r = 0; r < 8; r++) {
                float4 xv = *(const float4*)&xsh[r*DIMV + i];
                acc[r] = fmaf(xv.x, wv.x,
                         fmaf(xv.y, wv.y,
                         fmaf(xv.z, wv.z,
                         fmaf(xv.w, wv.w, acc[r]))));
            }
        }
        #pragma unroll
        for (int r = 0; r < 8; r++) {
            float a = acc[r];
            #pragma unroll
            for (int o = 16; o; o >>= 1) a += __shfl_xor_sync(0xffffffffu, a, o);
            if (lane == 0) {
                int row = row0 + r;
                if (hidx < H) {
                    float z  = a + dt_bias[hidx];
                    float sp = (z > 20.f) ? z : log1pf(expf(z));
                    g_g[row*H + hidx] = expf(-expf(A_log[hidx]) * sp);
                } else {
                    g_beta[row*H + (hidx - H)] = 1.f / (1.f + expf(-a));
                }
            }
        }
    }
}

// ---------------- fused causal conv(K=4)+SiLU (+L2 norm for q,k) --------
struct ConvPtrs {
    const float* in[3];
    float*       out[3];
    const float* cw[3];
    const float* cb[3];
};

__global__ void conv_kernel(ConvPtrs P)
{
    int which = blockIdx.z;
    const float* in  = P.in[which];
    float*       out = P.out[which];
    int bs  = blockIdx.x;
    int h   = blockIdx.y;
    int tid = threadIdx.x;
    int c   = h*128 + tid;
    int s   = bs & (SS - 1);
    const float* wr = P.cw[which] + (size_t)c*KCONV;
    float acc = P.cb[which][c];
    #pragma unroll
    for (int j = 0; j < KCONV; j++) {
        int sp = s - (KCONV-1) + j;
        if (sp >= 0)
            acc = fmaf(in[(size_t)(bs - (KCONV-1) + j)*2048 + c], wr[j], acc);
    }
    acc = acc / (1.f + expf(-acc));   // SiLU
    if (which < 2) {                  // q,k: per-head L2 norm
        float ss = acc*acc;
        #pragma unroll
        for (int o = 16; o; o >>= 1) ss += __shfl_xor_sync(0xffffffffu, ss, o);
        __shared__ float sred[4];
        if ((tid & 31) == 0) sred[tid >> 5] = ss;
        __syncthreads();
        float tot = sred[0] + sred[1] + sred[2] + sred[3];
        acc = acc / fmaxf(sqrtf(tot), 1e-12f);
    }
    out[(size_t)bs*2048 + c] = acc;
}

// ---------------- gated delta-rule recurrence (round-3 version) ----------
__global__ __launch_bounds__(128) void rec_kernel()
{
    int bid    = blockIdx.x;
    int cg     = bid & 3;
    int bh     = bid >> 2;
    int h      = bh & (H - 1);
    int b      = bh >> 4;
    int tid    = threadIdx.x;
    int kseg   = tid >> 5;
    int colIdx = tid & 31;

    const float* kp = g_kn   + (size_t)b*SS*KD + h*DK;
    const float* qp = g_qn   + (size_t)b*SS*KD + h*DK;
    const float* vp = g_vc   + (size_t)b*SS*VD + h*DV + cg*32;
    const float* gp = g_g    + (size_t)b*SS*H  + h;
    const float* bp = g_beta + (size_t)b*SS*H  + h;
    float*       op = g_o    + (size_t)b*SS*VD + h*DV + cg*32;

    __shared__ __align__(16) float ksm[2][128];
    __shared__ __align__(16) float qsm[2][128];
    __shared__ float vsm[2][32];
    __shared__ float gsm[2], bsm[2];
    __shared__ float redr[128], redo[128];

    float St[32];
    #pragma unroll
    for (int i = 0; i < 32; i++) St[i] = 0.f;

    ksm[0][tid] = kp[tid];
    qsm[0][tid] = qp[tid];
    if (tid < 32) vsm[0][tid] = vp[tid];
    if (tid == 0) { gsm[0] = gp[0]; bsm[0] = bp[0]; }
    __syncthreads();

    for (int t = 0; t < SS; t++) {
        int cur = t & 1, nxt = cur ^ 1;
        float knr = 0.f, qnr = 0.f, vnr = 0.f, gnr = 0.f, bnr = 0.f;
        if (t + 1 < SS) {
            knr = kp[(size_t)(t+1)*KD + tid];
            qnr = qp[(size_t)(t+1)*KD + tid];
            if (tid < 32) vnr = vp[(size_t)(t+1)*VD + tid];
            if (tid == 0) { gnr = gp[(size_t)(t+1)*H]; bnr = bp[(size_t)(t+1)*H]; }
        }
        float gv   = gsm[cur];
        float bv   = bsm[cur];
        float vval = vsm[cur][colIdx];
        const float* kc = &ksm[cur][kseg*32];
        const float* qc = &qsm[cur][kseg*32];

        float r0=0.f, r1=0.f, r2=0.f, r3=0.f;
        #pragma unroll
        for (int i = 0; i < 32; i += 4) {
            float4 k4 = *(const float4*)(kc + i);
            r0 = fmaf(St[i],   k4.x, r0);
            r1 = fmaf(St[i+1], k4.y, r1);
            r2 = fmaf(St[i+2], k4.z, r2);
            r3 = fmaf(St[i+3], k4.w, r3);
        }
        redr[tid] = (r0 + r1) + (r2 + r3);
        __syncthreads();
        float rs  = redr[colIdx] + redr[colIdx+32] + redr[colIdx+64] + redr[colIdx+96];
        float err = vval - gv*rs;
        float w   = bv*err;

        float o0=0.f, o1=0.f, o2=0.f, o3=0.f;
        #pragma unroll
        for (int i = 0; i < 32; i += 4) {
            float4 k4 = *(const float4*)(kc + i);
            float4 q4 = *(const float4*)(qc + i);
            St[i]   = fmaf(gv, St[i],   k4.x*w); o0 = fmaf(St[i],   q4.x, o0);
            St[i+1] = fmaf(gv, St[i+1], k4.y*w); o1 = fmaf(St[i+1], q4.y, o1);
            St[i+2] = fmaf(gv, St[i+2], k4.z*w); o2 = fmaf(St[i+2], q4.z, o2);
            St[i+3] = fmaf(gv, St[i+3], k4.w*w); o3 = fmaf(St[i+3], q4.w, o3);
        }
        redo[tid] = (o0 + o1) + (o2 + o3);

        if (t + 1 < SS) {
            ksm[nxt][tid] = knr;
            qsm[nxt][tid] = qnr;
            if (tid < 32) vsm[nxt][tid] = vnr;
            if (tid == 0) { gsm[nxt] = gnr; bsm[nxt] = bnr; }
        }
        __syncthreads();
        if (kseg == 0) {
            float os = redo[colIdx] + redo[colIdx+32] + redo[colIdx+64] + redo[colIdx+96];
            op[(size_t)t*VD + colIdx] = os;
        }
    }
}

// ---------------- RMSNorm + gate (silu(x@Wg.T)), emits tf32 bits ---------
__global__ void rmsnorm_gate_kernel(const float* __restrict__ norm_w)
{
    int row = blockIdx.x;
    int tid = threadIdx.x;   // 256
    float vals[8];
    float ss = 0.f;
    #pragma unroll
    for (int i = 0; i < 8; i++) {
        float v = g_o[(size_t)row*VD + i*256 + tid];
        vals[i] = v;
        ss += v*v;
    }
    #pragma unroll
    for (int o = 16; o; o >>= 1) ss += __shfl_xor_sync(0xffffffffu, ss, o);
    __shared__ float sred[8];
    if ((tid & 31) == 0) sred[tid >> 5] = ss;
    __syncthreads();
    float tot = 0.f;
    #pragma unroll
    for (int i = 0; i < 8; i++) tot += sred[i];
    float scale = rsqrtf(tot * (1.f/VD) + 1e-6f);
    #pragma unroll
    for (int i = 0; i < 8; i++) {
        int c = i*256 + tid;
        float gl = g_glin[(size_t)row*VD + c];
        float r  = vals[i] * scale * norm_w[c] * (gl / (1.f + expf(-gl)));
        g_ogt[(size_t)row*VD + c] = f2tf32(r);
    }
}

// ---------------- launch (fork/join: ab + Wo-cvt overlap proj GEMM) ------
extern "C" void kernel_launch(void* const* d_in, const int* in_sizes, int n_in,
                              void* d_out, int out_size)
{
    const float* x       = (const float*)d_in[0];
    const float* Wq      = (const float*)d_in[1];
    const float* Wk      = (const float*)d_in[2];
    const float* Wv      = (const float*)d_in[3];
    const float* Wa      = (const float*)d_in[4];
    const float* Wb      = (const float*)d_in[5];
    const float* Wg      = (const float*)d_in[6];
    const float* Wo      = (const float*)d_in[7];
    const float* cw_q    = (const float*)d_in[8];
    const float* cb_q    = (const float*)d_in[9];
    const float* cw_k    = (const float*)d_in[10];
    const float* cb_k    = (const float*)d_in[11];
    const float* cw_v    = (const float*)d_in[12];
    const float* cb_v    = (const float*)d_in[13];
    const float* A_log   = (const float*)d_in[14];
    const float* dt_bias = (const float*)d_in[15];
    const float* norm_w  = (const float*)d_in[16];

    float *qlin, *klin, *vlin, *glin, *qn, *kn, *vc;
    uint32_t *xt, *w4, *wot, *ogt;
    cudaGetSymbolAddress((void**)&qlin, g_qlin);
    cudaGetSymbolAddress((void**)&klin, g_klin);
    cudaGetSymbolAddress((void**)&vlin, g_vlin);
    cudaGetSymbolAddress((void**)&glin, g_glin);
    cudaGetSymbolAddress((void**)&qn,   g_qn);
    cudaGetSymbolAddress((void**)&kn,   g_kn);
    cudaGetSymbolAddress((void**)&vc,   g_vc);
    cudaGetSymbolAddress((void**)&xt,   g_xt);
    cudaGetSymbolAddress((void**)&w4,   g_w4);
    cudaGetSymbolAddress((void**)&wot,  g_wot);
    cudaGetSymbolAddress((void**)&ogt,  g_ogt);

    static int inited = 0;
    static cudaStream_t s2;
    static cudaEvent_t  evFork, evSide;
    if (!inited) {
        cudaFuncSetAttribute(mma_gemm_tf32,
                             cudaFuncAttributeMaxDynamicSharedMemorySize,
                             4*STAGE_WORDS*4);
        cudaFuncSetAttribute(ab_kernel,
                             cudaFuncAttributeMaxDynamicSharedMemorySize,
                             8*DIMV*4);
        cudaStreamCreateWithFlags(&s2, cudaStreamNonBlocking);
        cudaEventCreateWithFlags(&evFork, cudaEventDisableTiming);
        cudaEventCreateWithFlags(&evSide, cudaEventDisableTiming);
        inited = 1;
    }
    size_t gemm_smem = 4*STAGE_WORDS*4;   // 73728 B

    // ---- fork: side stream runs ab_kernel + cvt(Wo), needing only inputs
    cudaEventRecord(evFork, 0);
    cudaStreamWaitEvent(s2, evFork, 0);
    ab_kernel<<<BS/8, 256, 8*DIMV*4, s2>>>(x, Wa, Wb, A_log, dt_bias);
    cvt_tf32_kernel<<<(DIMV*VD)/1024, 256, 0, s2>>>(Wo, wot);
    cudaEventRecord(evSide, s2);

    // ---- main stream: tf32 conversions for proj GEMM operands
    cvt_tf32_kernel<<<(BS*DIMV)/1024, 256>>>(x, xt);
    CvtPtrs cp;
    cp.src[0]=Wq; cp.dst[0]=w4 + 0*(size_t)KD*DIMV;
    cp.src[1]=Wk; cp.dst[1]=w4 + 1*(size_t)KD*DIMV;
    cp.src[2]=Wv; cp.dst[2]=w4 + 2*(size_t)KD*DIMV;
    cp.src[3]=Wg; cp.dst[3]=w4 + 3*(size_t)KD*DIMV;
    cvt_w_kernel<<<dim3((KD*DIMV)/1024, 4), 256>>>(cp);

    // fused q/k/v/g projection GEMM
    GemmPtrs P;
    P.Bw[0] = w4 + 0*(size_t)KD*DIMV; P.C[0] = qlin;
    P.Bw[1] = w4 + 1*(size_t)KD*DIMV; P.C[1] = klin;
    P.Bw[2] = w4 + 2*(size_t)KD*DIMV; P.C[2] = vlin;
    P.Bw[3] = w4 + 3*(size_t)KD*DIMV; P.C[3] = glin;
    mma_gemm_tf32<<<dim3(64, 32), 256, gemm_smem>>>(xt, P, DIMV, KD);

    ConvPtrs cvp;
    cvp.in[0]=qlin; cvp.out[0]=qn; cvp.cw[0]=cw_q; cvp.cb[0]=cb_q;
    cvp.in[1]=klin; cvp.out[1]=kn; cvp.cw[1]=cw_k; cvp.cb[1]=cb_k;
    cvp.in[2]=vlin; cvp.out[2]=vc; cvp.cw[2]=cw_v; cvp.cb[2]=cb_v;
    conv_kernel<<<dim3(BS, H, 3), 128>>>(cvp);

    // ---- join: rec needs g/beta (side stream); final GEMM needs wot
    cudaStreamWaitEvent(0, evSide, 0);

    rec_kernel<<<BB*H*4, 128>>>();

    rmsnorm_gate_kernel<<<BS, 256>>>(norm_w);

    // output GEMM
    GemmPtrs Po;
    for (int i = 0; i < 4; i++) { Po.Bw[i] = wot; Po.C[i] = (float*)d_out; }
    mma_gemm_tf32<<<dim3(16, 32), 256, gemm_smem>>>(ogt, Po, VD, DIMV);
}

// round 16
// speedup vs baseline: 1.0023x; 1.0023x over previous
#include <cuda_runtime.h>
#include <math.h>
#include <stdint.h>

#define BB    2
#define SS    2048
#define DIMV  2048
#define H     16
#define DK    128
#define DV    128
#define KD    2048
#define VD    2048
#define KCONV 4
#define BS    (BB*SS)   // 4096

// ---------------- scratch (static __device__, no allocs) ----------------
__device__ float    g_qlin[BS*KD];
__device__ float    g_klin[BS*KD];
__device__ float    g_vlin[BS*VD];
__device__ float    g_glin[BS*VD];
__device__ float    g_qn[BS*KD];
__device__ float    g_kn[BS*KD];
__device__ float    g_vc[BS*VD];
__device__ float    g_o[BS*VD];
__device__ float    g_g[BS*H];
__device__ float    g_beta[BS*H];
__device__ uint32_t g_xt[BS*DIMV];        // x in tf32 bits
__device__ uint32_t g_w4[4*KD*DIMV];      // Wq|Wk|Wv|Wg in tf32 bits
__device__ uint32_t g_wot[DIMV*VD];       // Wo in tf32 bits
__device__ uint32_t g_ogt[BS*VD];         // rmsnorm*gate output in tf32 bits

__device__ __forceinline__ uint32_t f2tf32(float x) {
    uint32_t r;
    asm("cvt.rna.tf32.f32 %0, %1;" : "=r"(r) : "f"(x));
    return r;
}

// ---------------- fp32 -> tf32 conversions ----------------
__global__ void cvt_tf32_kernel(const float* __restrict__ in, uint32_t* __restrict__ out)
{
    size_t i = ((size_t)blockIdx.x * 256 + threadIdx.x) * 4;
    float4 v = *(const float4*)(in + i);
    uint4 u;
    u.x = f2tf32(v.x); u.y = f2tf32(v.y); u.z = f2tf32(v.z); u.w = f2tf32(v.w);
    *(uint4*)(out + i) = u;
}

struct CvtPtrs { const float* src[4]; uint32_t* dst[4]; };

__global__ void cvt_w_kernel(CvtPtrs P)
{
    int m = blockIdx.y;
    const float* in  = P.src[m];
    uint32_t*    out = P.dst[m];
    size_t i = ((size_t)blockIdx.x * 256 + threadIdx.x) * 4;
    float4 v = *(const float4*)(in + i);
    uint4 u;
    u.x = f2tf32(v.x); u.y = f2tf32(v.y); u.z = f2tf32(v.z); u.w = f2tf32(v.w);
    *(uint4*)(out + i) = u;
}

// ---------------- TF32 tensor-core GEMM NT, cp.async double-buffered ----
// (round-3 configuration: 256 thr, 8 warps x (64x32), BK=32, 2 stages)
#define SMS 36            // word stride: 36 mod 32 = 4 -> LDS bank = lane perm
#define STAGE_WORDS (128*SMS)

#define MMA_TF32(d, a, b)                                                      \
    asm volatile(                                                              \
        "mma.sync.aligned.m16n8k8.row.col.f32.tf32.tf32.f32 "                  \
        "{%0,%1,%2,%3},{%4,%5,%6,%7},{%8,%9},{%0,%1,%2,%3};"                   \
        : "+f"(d[0]), "+f"(d[1]), "+f"(d[2]), "+f"(d[3])                       \
        : "r"(a[0]), "r"(a[1]), "r"(a[2]), "r"(a[3]), "r"(b[0]), "r"(b[1]))

__device__ __forceinline__ void cpa16(uint32_t saddr, const void* gptr) {
    asm volatile("cp.async.ca.shared.global [%0], [%1], 16;\n" :: "r"(saddr), "l"(gptr));
}

struct GemmPtrs {
    const uint32_t* Bw[4];
    float*          C[4];
};

__global__ __launch_bounds__(256, 2) void mma_gemm_tf32(
    const uint32_t* __restrict__ A, GemmPtrs P, int K, int N)
{
    extern __shared__ uint32_t smem[];
    uint32_t* As = smem;                     // [2][STAGE_WORDS]
    uint32_t* Bs = smem + 2*STAGE_WORDS;     // [2][STAGE_WORDS]

    int buf = blockIdx.x >> 4;
    int nb  = blockIdx.x & 15;
    const uint32_t* Bw = P.Bw[buf];
    float*          C  = P.C[buf];

    int tid   = threadIdx.x;
    int lane  = tid & 31;
    int warp  = tid >> 5;
    int warpM = warp >> 2;
    int warpN = warp & 3;
    int mBase = blockIdx.y * 128;
    int nBase = nb * 128;
    int g = lane >> 2;
    int t = lane & 3;

    uint32_t sA = (uint32_t)__cvta_generic_to_shared(As);
    uint32_t sB = (uint32_t)__cvta_generic_to_shared(Bs);

    float acc[4][4][4];
    #pragma unroll
    for (int i = 0; i < 4; i++)
        #pragma unroll
        for (int j = 0; j < 4; j++)
            #pragma unroll
            for (int r = 0; r < 4; r++) acc[i][j][r] = 0.f;

    #define LOAD_STAGE(stg, kb)                                                 \
        do {                                                                    \
            _Pragma("unroll")                                                   \
            for (int j = 0; j < 4; j++) {                                       \
                int idx = tid + j * 256;                                        \
                int row = idx >> 3;                                             \
                int kc  = (idx & 7) << 2;                                       \
                cpa16(sA + ((stg)*STAGE_WORDS + row*SMS + kc)*4,                \
                      &A[(size_t)(mBase + row)*K + (kb) + kc]);                 \
                cpa16(sB + ((stg)*STAGE_WORDS + row*SMS + kc)*4,                \
                      &Bw[(size_t)(nBase + row)*K + (kb) + kc]);                \
            }                                                                   \
            asm volatile("cp.async.commit_group;\n");                           \
        } while (0)

    LOAD_STAGE(0, 0);
    int NIT = K >> 5;
    for (int it = 0; it < NIT; it++) {
        int cur = it & 1;
        if (it + 1 < NIT) {
            LOAD_STAGE(cur ^ 1, (it + 1) << 5);
            asm volatile("cp.async.wait_group 1;\n");
        } else {
            asm volatile("cp.async.wait_group 0;\n");
        }
        __syncthreads();

        const uint32_t* Ac = As + cur*STAGE_WORDS;
        const uint32_t* Bc = Bs + cur*STAGE_WORDS;
        #pragma unroll
        for (int ks = 0; ks < 4; ks++) {
            int k0 = ks * 8;
            uint32_t af[4][4], bf[4][2];
            #pragma unroll
            for (int mt = 0; mt < 4; mt++) {
                int m = warpM*64 + mt*16;
                af[mt][0] = Ac[(m + g    )*SMS + k0 + t];
                af[mt][1] = Ac[(m + g + 8)*SMS + k0 + t];
                af[mt][2] = Ac[(m + g    )*SMS + k0 + t + 4];
                af[mt][3] = Ac[(m + g + 8)*SMS + k0 + t + 4];
            }
            #pragma unroll
            for (int nt = 0; nt < 4; nt++) {
                int n = warpN*32 + nt*8;
                bf[nt][0] = Bc[(n + g)*SMS + k0 + t];
                bf[nt][1] = Bc[(n + g)*SMS + k0 + t + 4];
            }
            #pragma unroll
            for (int mt = 0; mt < 4; mt++)
                #pragma unroll
                for (int nt = 0; nt < 4; nt++)
                    MMA_TF32(acc[mt][nt], af[mt], bf[nt]);
        }
        __syncthreads();
    }

    #pragma unroll
    for (int mt = 0; mt < 4; mt++) {
        #pragma unroll
        for (int nt = 0; nt < 4; nt++) {
            int row = mBase + warpM*64 + mt*16 + g;
            int col = nBase + warpN*32 + nt*8 + 2*t;
            *(float2*)&C[(size_t)row * N + col] =
                make_float2(acc[mt][nt][0], acc[mt][nt][1]);
            *(float2*)&C[(size_t)(row + 8) * N + col] =
                make_float2(acc[mt][nt][2], acc[mt][nt][3]);
        }
    }
}

// ---------------- a/b projections, 8 rows per block ----------------
__global__ __launch_bounds__(256) void ab_kernel(
    const float* __restrict__ x, const float* __restrict__ Wa,
    const float* __restrict__ Wb, const float* __restrict__ A_log,
    const float* __restrict__ dt_bias)
{
    extern __shared__ float xsh[];   // 8*2048 floats = 64KB
    int row0 = blockIdx.x * 8;
    int tid  = threadIdx.x;
    int lane = tid & 31;
    int warp = tid >> 5;

    #pragma unroll
    for (int j = 0; j < 16; j++) {
        int idx = tid + j*256;          // 0..4095 float4s
        int r   = idx >> 9;             // 512 float4 per row
        int cw  = idx & 511;
        ((float4*)xsh)[idx] =
            ((const float4*)(x + (size_t)(row0 + r)*DIMV))[cw];
    }
    __syncthreads();

    #pragma unroll
    for (int hh = 0; hh < 4; hh++) {
        int hidx = warp*4 + hh;                 // 0..31
        const float* wrow = (hidx < H) ? (Wa + (size_t)hidx*DIMV)
                                       : (Wb + (size_t)(hidx - H)*DIMV);
        float acc[8];
        #pragma unroll
        for (int r = 0; r < 8; r++) acc[r] = 0.f;
        for (int i = lane*4; i < DIMV; i += 128) {
            float4 wv = *(const float4*)&wrow[i];
            #pragma unroll
            for (int r = 0; r < 8; r++) {
                float4 xv = *(const float4*)&xsh[r*DIMV + i];
                acc[r] = fmaf(xv.x, wv.x,
                         fmaf(xv.y, wv.y,
                         fmaf(xv.z, wv.z,
                         fmaf(xv.w, wv.w, acc[r]))));
            }
        }
        #pragma unroll
        for (int r = 0; r < 8; r++) {
            float a = acc[r];
            #pragma unroll
            for (int o = 16; o; o >>= 1) a += __shfl_xor_sync(0xffffffffu, a, o);
            if (lane == 0) {
                int row = row0 + r;
                if (hidx < H) {
                    float z  = a + dt_bias[hidx];
                    float sp = (z > 20.f) ? z : log1pf(expf(z));
                    g_g[row*H + hidx] = expf(-expf(A_log[hidx]) * sp);
                } else {
                    g_beta[row*H + (hidx - H)] = 1.f / (1.f + expf(-a));
                }
            }
        }
    }
}

// ---------------- fused causal conv(K=4)+SiLU (+L2 norm for q,k) --------
struct ConvPtrs {
    const float* in[3];
    float*       out[3];
    const float* cw[3];
    const float* cb[3];
};

__global__ void conv_kernel(ConvPtrs P)
{
    int which = blockIdx.z;
    const float* in  = P.in[which];
    float*       out = P.out[which];
    int bs  = blockIdx.x;
    int h   = blockIdx.y;
    int tid = threadIdx.x;
    int c   = h*128 + tid;
    int s   = bs & (SS - 1);
    const float* wr = P.cw[which] + (size_t)c*KCONV;
    float acc = P.cb[which][c];
    #pragma unroll
    for (int j = 0; j < KCONV; j++) {
        int sp = s - (KCONV-1) + j;
        if (sp >= 0)
            acc = fmaf(in[(size_t)(bs - (KCONV-1) + j)*2048 + c], wr[j], acc);
    }
    acc = acc / (1.f + expf(-acc));   // SiLU
    if (which < 2) {                  // q,k: per-head L2 norm
        float ss = acc*acc;
        #pragma unroll
        for (int o = 16; o; o >>= 1) ss += __shfl_xor_sync(0xffffffffu, ss, o);
        __shared__ float sred[4];
        if ((tid & 31) == 0) sred[tid >> 5] = ss;
        __syncthreads();
        float tot = sred[0] + sred[1] + sred[2] + sred[3];
        acc = acc / fmaxf(sqrtf(tot), 1e-12f);
    }
    out[(size_t)bs*2048 + c] = acc;
}

// ---------------- gated delta-rule recurrence (round-3 version) ----------
__global__ __launch_bounds__(128) void rec_kernel()
{
    int bid    = blockIdx.x;
    int cg     = bid & 3;
    int bh     = bid >> 2;
    int h      = bh & (H - 1);
    int b      = bh >> 4;
    int tid    = threadIdx.x;
    int kseg   = tid >> 5;
    int colIdx = tid & 31;

    const float* kp = g_kn   + (size_t)b*SS*KD + h*DK;
    const float* qp = g_qn   + (size_t)b*SS*KD + h*DK;
    const float* vp = g_vc   + (size_t)b*SS*VD + h*DV + cg*32;
    const float* gp = g_g    + (size_t)b*SS*H  + h;
    const float* bp = g_beta + (size_t)b*SS*H  + h;
    float*       op = g_o    + (size_t)b*SS*VD + h*DV + cg*32;

    __shared__ __align__(16) float ksm[2][128];
    __shared__ __align__(16) float qsm[2][128];
    __shared__ float vsm[2][32];
    __shared__ float gsm[2], bsm[2];
    __shared__ float redr[128], redo[128];

    float St[32];
    #pragma unroll
    for (int i = 0; i < 32; i++) St[i] = 0.f;

    ksm[0][tid] = kp[tid];
    qsm[0][tid] = qp[tid];
    if (tid < 32) vsm[0][tid] = vp[tid];
    if (tid == 0) { gsm[0] = gp[0]; bsm[0] = bp[0]; }
    __syncthreads();

    for (int t = 0; t < SS; t++) {
        int cur = t & 1, nxt = cur ^ 1;
        float knr = 0.f, qnr = 0.f, vnr = 0.f, gnr = 0.f, bnr = 0.f;
        if (t + 1 < SS) {
            knr = kp[(size_t)(t+1)*KD + tid];
            qnr = qp[(size_t)(t+1)*KD + tid];
            if (tid < 32) vnr = vp[(size_t)(t+1)*VD + tid];
            if (tid == 0) { gnr = gp[(size_t)(t+1)*H]; bnr = bp[(size_t)(t+1)*H]; }
        }
        float gv   = gsm[cur];
        float bv   = bsm[cur];
        float vval = vsm[cur][colIdx];
        const float* kc = &ksm[cur][kseg*32];
        const float* qc = &qsm[cur][kseg*32];

        float r0=0.f, r1=0.f, r2=0.f, r3=0.f;
        #pragma unroll
        for (int i = 0; i < 32; i += 4) {
            float4 k4 = *(const float4*)(kc + i);
            r0 = fmaf(St[i],   k4.x, r0);
            r1 = fmaf(St[i+1], k4.y, r1);
            r2 = fmaf(St[i+2], k4.z, r2);
            r3 = fmaf(St[i+3], k4.w, r3);
        }
        redr[tid] = (r0 + r1) + (r2 + r3);
        __syncthreads();
        float rs  = redr[colIdx] + redr[colIdx+32] + redr[colIdx+64] + redr[colIdx+96];
        float err = vval - gv*rs;
        float w   = bv*err;

        float o0=0.f, o1=0.f, o2=0.f, o3=0.f;
        #pragma unroll
        for (int i = 0; i < 32; i += 4) {
            float4 k4 = *(const float4*)(kc + i);
            float4 q4 = *(const float4*)(qc + i);
            St[i]   = fmaf(gv, St[i],   k4.x*w); o0 = fmaf(St[i],   q4.x, o0);
            St[i+1] = fmaf(gv, St[i+1], k4.y*w); o1 = fmaf(St[i+1], q4.y, o1);
            St[i+2] = fmaf(gv, St[i+2], k4.z*w); o2 = fmaf(St[i+2], q4.z, o2);
            St[i+3] = fmaf(gv, St[i+3], k4.w*w); o3 = fmaf(St[i+3], q4.w, o3);
        }
        redo[tid] = (o0 + o1) + (o2 + o3);

        if (t + 1 < SS) {
            ksm[nxt][tid] = knr;
            qsm[nxt][tid] = qnr;
            if (tid < 32) vsm[nxt][tid] = vnr;
            if (tid == 0) { gsm[nxt] = gnr; bsm[nxt] = bnr; }
        }
        __syncthreads();
        if (kseg == 0) {
            float os = redo[colIdx] + redo[colIdx+32] + redo[colIdx+64] + redo[colIdx+96];
            op[(size_t)t*VD + colIdx] = os;
        }
    }
}

// ---------------- RMSNorm + gate (silu(x@Wg.T)), emits tf32 bits ---------
__global__ void rmsnorm_gate_kernel(const float* __restrict__ norm_w)
{
    int row = blockIdx.x;
    int tid = threadIdx.x;   // 256
    float vals[8];
    float ss = 0.f;
    #pragma unroll
    for (int i = 0; i < 8; i++) {
        float v = g_o[(size_t)row*VD + i*256 + tid];
        vals[i] = v;
        ss += v*v;
    }
    #pragma unroll
    for (int o = 16; o; o >>= 1) ss += __shfl_xor_sync(0xffffffffu, ss, o);
    __shared__ float sred[8];
    if ((tid & 31) == 0) sred[tid >> 5] = ss;
    __syncthreads();
    float tot = 0.f;
    #pragma unroll
    for (int i = 0; i < 8; i++) tot += sred[i];
    float scale = rsqrtf(tot * (1.f/VD) + 1e-6f);
    #pragma unroll
    for (int i = 0; i < 8; i++) {
        int c = i*256 + tid;
        float gl = g_glin[(size_t)row*VD + c];
        float r  = vals[i] * scale * norm_w[c] * (gl / (1.f + expf(-gl)));
        g_ogt[(size_t)row*VD + c] = f2tf32(r);
    }
}

// ---------------- launch ----------------
// Fork/join: side stream runs ab + cvt(Wo) + glin GEMM (not needed until
// rmsnorm), hidden behind main-stream qkv GEMM + conv + rec.
extern "C" void kernel_launch(void* const* d_in, const int* in_sizes, int n_in,
                              void* d_out, int out_size)
{
    const float* x       = (const float*)d_in[0];
    const float* Wq      = (const float*)d_in[1];
    const float* Wk      = (const float*)d_in[2];
    const float* Wv      = (const float*)d_in[3];
    const float* Wa      = (const float*)d_in[4];
    const float* Wb      = (const float*)d_in[5];
    const float* Wg      = (const float*)d_in[6];
    const float* Wo      = (const float*)d_in[7];
    const float* cw_q    = (const float*)d_in[8];
    const float* cb_q    = (const float*)d_in[9];
    const float* cw_k    = (const float*)d_in[10];
    const float* cb_k    = (const float*)d_in[11];
    const float* cw_v    = (const float*)d_in[12];
    const float* cb_v    = (const float*)d_in[13];
    const float* A_log   = (const float*)d_in[14];
    const float* dt_bias = (const float*)d_in[15];
    const float* norm_w  = (const float*)d_in[16];

    float *qlin, *klin, *vlin, *glin, *qn, *kn, *vc;
    uint32_t *xt, *w4, *wot, *ogt;
    cudaGetSymbolAddress((void**)&qlin, g_qlin);
    cudaGetSymbolAddress((void**)&klin, g_klin);
    cudaGetSymbolAddress((void**)&vlin, g_vlin);
    cudaGetSymbolAddress((void**)&glin, g_glin);
    cudaGetSymbolAddress((void**)&qn,   g_qn);
    cudaGetSymbolAddress((void**)&kn,   g_kn);
    cudaGetSymbolAddress((void**)&vc,   g_vc);
    cudaGetSymbolAddress((void**)&xt,   g_xt);
    cudaGetSymbolAddress((void**)&w4,   g_w4);
    cudaGetSymbolAddress((void**)&wot,  g_wot);
    cudaGetSymbolAddress((void**)&ogt,  g_ogt);

    static int inited = 0;
    static cudaStream_t s2;
    static cudaEvent_t  evFork, evCvt, evSide;
    if (!inited) {
        cudaFuncSetAttribute(mma_gemm_tf32,
                             cudaFuncAttributeMaxDynamicSharedMemorySize,
                             4*STAGE_WORDS*4);
        cudaFuncSetAttribute(ab_kernel,
                             cudaFuncAttributeMaxDynamicSharedMemorySize,
                             8*DIMV*4);
        cudaStreamCreateWithFlags(&s2, cudaStreamNonBlocking);
        cudaEventCreateWithFlags(&evFork, cudaEventDisableTiming);
        cudaEventCreateWithFlags(&evCvt,  cudaEventDisableTiming);
        cudaEventCreateWithFlags(&evSide, cudaEventDisableTiming);
        inited = 1;
    }
    size_t gemm_smem = 4*STAGE_WORDS*4;   // 73728 B

    // ---- fork: side stream starts with input-only work
    cudaEventRecord(evFork, 0);
    cudaStreamWaitEvent(s2, evFork, 0);
    ab_kernel<<<BS/8, 256, 8*DIMV*4, s2>>>(x, Wa, Wb, A_log, dt_bias);
    cvt_tf32_kernel<<<(DIMV*VD)/1024, 256, 0, s2>>>(Wo, wot);

    // ---- main stream: tf32 conversions (x + all 4 projection weights)
    cvt_tf32_kernel<<<(BS*DIMV)/1024, 256>>>(x, xt);
    CvtPtrs cp;
    cp.src[0]=Wq; cp.dst[0]=w4 + 0*(size_t)KD*DIMV;
    cp.src[1]=Wk; cp.dst[1]=w4 + 1*(size_t)KD*DIMV;
    cp.src[2]=Wv; cp.dst[2]=w4 + 2*(size_t)KD*DIMV;
    cp.src[3]=Wg; cp.dst[3]=w4 + 3*(size_t)KD*DIMV;
    cvt_w_kernel<<<dim3((KD*DIMV)/1024, 4), 256>>>(cp);
    cudaEventRecord(evCvt, 0);

    // side stream: glin GEMM once xt + Wg-tf32 are ready; overlaps conv+rec
    cudaStreamWaitEvent(s2, evCvt, 0);
    GemmPtrs Pg;
    Pg.Bw[0] = w4 + 3*(size_t)KD*DIMV; Pg.C[0] = glin;
    Pg.Bw[1] = Pg.Bw[0]; Pg.C[1] = glin;
    Pg.Bw[2] = Pg.Bw[0]; Pg.C[2] = glin;
    Pg.Bw[3] = Pg.Bw[0]; Pg.C[3] = glin;
    mma_gemm_tf32<<<dim3(16, 32), 256, gemm_smem, s2>>>(xt, Pg, DIMV, KD);
    cudaEventRecord(evSide, s2);

    // ---- main stream: q/k/v projection GEMM (grid.x=48 -> buf 0..2)
    GemmPtrs P;
    P.Bw[0] = w4 + 0*(size_t)KD*DIMV; P.C[0] = qlin;
    P.Bw[1] = w4 + 1*(size_t)KD*DIMV; P.C[1] = klin;
    P.Bw[2] = w4 + 2*(size_t)KD*DIMV; P.C[2] = vlin;
    P.Bw[3] = P.Bw[0];                P.C[3] = qlin;   // unused (grid.x=48)
    mma_gemm_tf32<<<dim3(48, 32), 256, gemm_smem>>>(xt, P, DIMV, KD);

    ConvPtrs cvp;
    cvp.in[0]=qlin; cvp.out[0]=qn; cvp.cw[0]=cw_q; cvp.cb[0]=cb_q;
    cvp.in[1]=klin; cvp.out[1]=kn; cvp.cw[1]=cw_k; cvp.cb[1]=cb_k;
    cvp.in[2]=vlin; cvp.out[2]=vc; cvp.cw[2]=cw_v; cvp.cb[2]=cb_v;
    conv_kernel<<<dim3(BS, H, 3), 128>>>(cvp);

    rec_kernel<<<BB*H*4, 128>>>();

    // ---- join: rmsnorm needs glin (+ wot later)
    cudaStreamWaitEvent(0, evSide, 0);

    rmsnorm_gate_kernel<<<BS, 256>>>(norm_w);

    // output GEMM
    GemmPtrs Po;
    for (int i = 0; i < 4; i++) { Po.Bw[i] = wot; Po.C[i] = (float*)d_out; }
    mma_gemm_tf32<<<dim3(16, 32), 256, gemm_smem>>>(ogt, Po, VD, DIMV);
}

// round 17
// speedup vs baseline: 1.0634x; 1.0610x over previous
#include <cuda_runtime.h>
#include <math.h>
#include <stdint.h>

#define BB    2
#define SS    2048
#define DIMV  2048
#define H     16
#define DK    128
#define DV    128
#define KD    2048
#define VD    2048
#define KCONV 4
#define BS    (BB*SS)   // 4096

// ---------------- scratch (static __device__, no allocs) ----------------
__device__ float    g_qlin[BS*KD];
__device__ float    g_klin[BS*KD];
__device__ float    g_vlin[BS*VD];
__device__ float    g_glin[BS*VD];
__device__ float    g_qn[BS*KD];
__device__ float    g_kn[BS*KD];
__device__ float    g_vc[BS*VD];
__device__ float    g_o[BS*VD];
__device__ float    g_g[BS*H];
__device__ float    g_beta[BS*H];
__device__ uint32_t g_xt[BS*DIMV];        // x in tf32 bits
__device__ uint32_t g_w4[4*KD*DIMV];      // Wq|Wk|Wv|Wg in tf32 bits
__device__ uint32_t g_wot[DIMV*VD];       // Wo in tf32 bits
__device__ uint32_t g_ogt[BS*VD];         // rmsnorm*gate output in tf32 bits

__device__ __forceinline__ uint32_t f2tf32(float x) {
    uint32_t r;
    asm("cvt.rna.tf32.f32 %0, %1;" : "=r"(r) : "f"(x));
    return r;
}

// ---------------- fp32 -> tf32 conversions ----------------
__global__ void cvt_tf32_kernel(const float* __restrict__ in, uint32_t* __restrict__ out)
{
    size_t i = ((size_t)blockIdx.x * 256 + threadIdx.x) * 4;
    float4 v = *(const float4*)(in + i);
    uint4 u;
    u.x = f2tf32(v.x); u.y = f2tf32(v.y); u.z = f2tf32(v.z); u.w = f2tf32(v.w);
    *(uint4*)(out + i) = u;
}

struct CvtPtrs { const float* src[4]; uint32_t* dst[4]; };

__global__ void cvt_w_kernel(CvtPtrs P)
{
    int m = blockIdx.y;
    const float* in  = P.src[m];
    uint32_t*    out = P.dst[m];
    size_t i = ((size_t)blockIdx.x * 256 + threadIdx.x) * 4;
    float4 v = *(const float4*)(in + i);
    uint4 u;
    u.x = f2tf32(v.x); u.y = f2tf32(v.y); u.z = f2tf32(v.z); u.w = f2tf32(v.w);
    *(uint4*)(out + i) = u;
}

// ---------------- TF32 tensor-core GEMM NT, cp.async double-buffered ----
// (round-3 configuration: 256 thr, 8 warps x (64x32), BK=32, 2 stages)
#define SMS 36            // word stride: 36 mod 32 = 4 -> LDS bank = lane perm
#define STAGE_WORDS (128*SMS)

#define MMA_TF32(d, a, b)                                                      \
    asm volatile(                                                              \
        "mma.sync.aligned.m16n8k8.row.col.f32.tf32.tf32.f32 "                  \
        "{%0,%1,%2,%3},{%4,%5,%6,%7},{%8,%9},{%0,%1,%2,%3};"                   \
        : "+f"(d[0]), "+f"(d[1]), "+f"(d[2]), "+f"(d[3])                       \
        : "r"(a[0]), "r"(a[1]), "r"(a[2]), "r"(a[3]), "r"(b[0]), "r"(b[1]))

__device__ __forceinline__ void cpa16(uint32_t saddr, const void* gptr) {
    asm volatile("cp.async.ca.shared.global [%0], [%1], 16;\n" :: "r"(saddr), "l"(gptr));
}

struct GemmPtrs {
    const uint32_t* Bw[4];
    float*          C[4];
};

__global__ __launch_bounds__(256, 2) void mma_gemm_tf32(
    const uint32_t* __restrict__ A, GemmPtrs P, int K, int N)
{
    extern __shared__ uint32_t smem[];
    uint32_t* As = smem;                     // [2][STAGE_WORDS]
    uint32_t* Bs = smem + 2*STAGE_WORDS;     // [2][STAGE_WORDS]

    int buf = blockIdx.x >> 4;
    int nb  = blockIdx.x & 15;
    const uint32_t* Bw = P.Bw[buf];
    float*          C  = P.C[buf];

    int tid   = threadIdx.x;
    int lane  = tid & 31;
    int warp  = tid >> 5;
    int warpM = warp >> 2;
    int warpN = warp & 3;
    int mBase = blockIdx.y * 128;
    int nBase = nb * 128;
    int g = lane >> 2;
    int t = lane & 3;

    uint32_t sA = (uint32_t)__cvta_generic_to_shared(As);
    uint32_t sB = (uint32_t)__cvta_generic_to_shared(Bs);

    float acc[4][4][4];
    #pragma unroll
    for (int i = 0; i < 4; i++)
        #pragma unroll
        for (int j = 0; j < 4; j++)
            #pragma unroll
            for (int r = 0; r < 4; r++) acc[i][j][r] = 0.f;

    #define LOAD_STAGE(stg, kb)                                                 \
        do {                                                                    \
            _Pragma("unroll")                                                   \
            for (int j = 0; j < 4; j++) {                                       \
                int idx = tid + j * 256;                                        \
                int row = idx >> 3;                                             \
                int kc  = (idx & 7) << 2;                                       \
                cpa16(sA + ((stg)*STAGE_WORDS + row*SMS + kc)*4,                \
                      &A[(size_t)(mBase + row)*K + (kb) + kc]);                 \
                cpa16(sB + ((stg)*STAGE_WORDS + row*SMS + kc)*4,                \
                      &Bw[(size_t)(nBase + row)*K + (kb) + kc]);                \
            }                                                                   \
            asm volatile("cp.async.commit_group;\n");                           \
        } while (0)

    LOAD_STAGE(0, 0);
    int NIT = K >> 5;
    for (int it = 0; it < NIT; it++) {
        int cur = it & 1;
        if (it + 1 < NIT) {
            LOAD_STAGE(cur ^ 1, (it + 1) << 5);
            asm volatile("cp.async.wait_group 1;\n");
        } else {
            asm volatile("cp.async.wait_group 0;\n");
        }
        __syncthreads();

        const uint32_t* Ac = As + cur*STAGE_WORDS;
        const uint32_t* Bc = Bs + cur*STAGE_WORDS;
        #pragma unroll
        for (int ks = 0; ks < 4; ks++) {
            int k0 = ks * 8;
            uint32_t af[4][4], bf[4][2];
            #pragma unroll
            for (int mt = 0; mt < 4; mt++) {
                int m = warpM*64 + mt*16;
                af[mt][0] = Ac[(m + g    )*SMS + k0 + t];
                af[mt][1] = Ac[(m + g + 8)*SMS + k0 + t];
                af[mt][2] = Ac[(m + g    )*SMS + k0 + t + 4];
                af[mt][3] = Ac[(m + g + 8)*SMS + k0 + t + 4];
            }
            #pragma unroll
            for (int nt = 0; nt < 4; nt++) {
                int n = warpN*32 + nt*8;
                bf[nt][0] = Bc[(n + g)*SMS + k0 + t];
                bf[nt][1] = Bc[(n + g)*SMS + k0 + t + 4];
            }
            #pragma unroll
            for (int mt = 0; mt < 4; mt++)
                #pragma unroll
                for (int nt = 0; nt < 4; nt++)
                    MMA_TF32(acc[mt][nt], af[mt], bf[nt]);
        }
        __syncthreads();
    }

    #pragma unroll
    for (int mt = 0; mt < 4; mt++) {
        #pragma unroll
        for (int nt = 0; nt < 4; nt++) {
            int row = mBase + warpM*64 + mt*16 + g;
            int col = nBase + warpN*32 + nt*8 + 2*t;
            *(float2*)&C[(size_t)row * N + col] =
                make_float2(acc[mt][nt][0], acc[mt][nt][1]);
            *(float2*)&C[(size_t)(row + 8) * N + col] =
                make_float2(acc[mt][nt][2], acc[mt][nt][3]);
        }
    }
}

// ---------------- a/b projections, 8 rows per block ----------------
__global__ __launch_bounds__(256) void ab_kernel(
    const float* __restrict__ x, const float* __restrict__ Wa,
    const float* __restrict__ Wb, const float* __restrict__ A_log,
    const float* __restrict__ dt_bias)
{
    extern __shared__ float xsh[];   // 8*2048 floats = 64KB
    int row0 = blockIdx.x * 8;
    int tid  = threadIdx.x;
    int lane = tid & 31;
    int warp = tid >> 5;

    #pragma unroll
    for (int j = 0; j < 16; j++) {
        int idx = tid + j*256;          // 0..4095 float4s
        int r   = idx >> 9;             // 512 float4 per row
        int cw  = idx & 511;
        ((float4*)xsh)[idx] =
            ((const float4*)(x + (size_t)(row0 + r)*DIMV))[cw];
    }
    __syncthreads();

    #pragma unroll
    for (int hh = 0; hh < 4; hh++) {
        int hidx = warp*4 + hh;                 // 0..31
        const float* wrow = (hidx < H) ? (Wa + (size_t)hidx*DIMV)
                                       : (Wb + (size_t)(hidx - H)*DIMV);
        float acc[8];
        #pragma unroll
        for (int r = 0; r < 8; r++) acc[r] = 0.f;
        for (int i = lane*4; i < DIMV; i += 128) {
            float4 wv = *(const float4*)&wrow[i];
            #pragma unroll
            for (int r = 0; r < 8; r++) {
                float4 xv = *(const float4*)&xsh[r*DIMV + i];
                acc[r] = fmaf(xv.x, wv.x,
                         fmaf(xv.y, wv.y,
                         fmaf(xv.z, wv.z,
                         fmaf(xv.w, wv.w, acc[r]))));
            }
        }
        #pragma unroll
        for (int r = 0; r < 8; r++) {
            float a = acc[r];
            #pragma unroll
            for (int o = 16; o; o >>= 1) a += __shfl_xor_sync(0xffffffffu, a, o);
            if (lane == 0) {
                int row = row0 + r;
                if (hidx < H) {
                    float z  = a + dt_bias[hidx];
                    float sp = (z > 20.f) ? z : log1pf(expf(z));
                    g_g[row*H + hidx] = expf(-expf(A_log[hidx]) * sp);
                } else {
                    g_beta[row*H + (hidx - H)] = 1.f / (1.f + expf(-a));
                }
            }
        }
    }
}

// ---------------- fused causal conv(K=4)+SiLU (+L2 norm for q,k) --------
struct ConvPtrs {
    const float* in[3];
    float*       out[3];
    const float* cw[3];
    const float* cb[3];
};

__global__ void conv_kernel(ConvPtrs P)
{
    int which = blockIdx.z;
    const float* in  = P.in[which];
    float*       out = P.out[which];
    int bs  = blockIdx.x;
    int h   = blockIdx.y;
    int tid = threadIdx.x;
    int c   = h*128 + tid;
    int s   = bs & (SS - 1);
    const float* wr = P.cw[which] + (size_t)c*KCONV;
    float acc = P.cb[which][c];
    #pragma unroll
    for (int j = 0; j < KCONV; j++) {
        int sp = s - (KCONV-1) + j;
        if (sp >= 0)
            acc = fmaf(in[(size_t)(bs - (KCONV-1) + j)*2048 + c], wr[j], acc);
    }
    acc = acc / (1.f + expf(-acc));   // SiLU
    if (which < 2) {                  // q,k: per-head L2 norm
        float ss = acc*acc;
        #pragma unroll
        for (int o = 16; o; o >>= 1) ss += __shfl_xor_sync(0xffffffffu, ss, o);
        __shared__ float sred[4];
        if ((tid & 31) == 0) sred[tid >> 5] = ss;
        __syncthreads();
        float tot = sred[0] + sred[1] + sred[2] + sred[3];
        acc = acc / fmaxf(sqrtf(tot), 1e-12f);
    }
    out[(size_t)bs*2048 + c] = acc;
}

// ---------------- gated delta-rule recurrence (round-3 version) ----------
__global__ __launch_bounds__(128) void rec_kernel()
{
    int bid    = blockIdx.x;
    int cg     = bid & 3;
    int bh     = bid >> 2;
    int h      = bh & (H - 1);
    int b      = bh >> 4;
    int tid    = threadIdx.x;
    int kseg   = tid >> 5;
    int colIdx = tid & 31;

    const float* kp = g_kn   + (size_t)b*SS*KD + h*DK;
    const float* qp = g_qn   + (size_t)b*SS*KD + h*DK;
    const float* vp = g_vc   + (size_t)b*SS*VD + h*DV + cg*32;
    const float* gp = g_g    + (size_t)b*SS*H  + h;
    const float* bp = g_beta + (size_t)b*SS*H  + h;
    float*       op = g_o    + (size_t)b*SS*VD + h*DV + cg*32;

    __shared__ __align__(16) float ksm[2][128];
    __shared__ __align__(16) float qsm[2][128];
    __shared__ float vsm[2][32];
    __shared__ float gsm[2], bsm[2];
    __shared__ float redr[128], redo[128];

    float St[32];
    #pragma unroll
    for (int i = 0; i < 32; i++) St[i] = 0.f;

    ksm[0][tid] = kp[tid];
    qsm[0][tid] = qp[tid];
    if (tid < 32) vsm[0][tid] = vp[tid];
    if (tid == 0) { gsm[0] = gp[0]; bsm[0] = bp[0]; }
    __syncthreads();

    for (int t = 0; t < SS; t++) {
        int cur = t & 1, nxt = cur ^ 1;
        float knr = 0.f, qnr = 0.f, vnr = 0.f, gnr = 0.f, bnr = 0.f;
        if (t + 1 < SS) {
            knr = kp[(size_t)(t+1)*KD + tid];
            qnr = qp[(size_t)(t+1)*KD + tid];
            if (tid < 32) vnr = vp[(size_t)(t+1)*VD + tid];
            if (tid == 0) { gnr = gp[(size_t)(t+1)*H]; bnr = bp[(size_t)(t+1)*H]; }
        }
        float gv   = gsm[cur];
        float bv   = bsm[cur];
        float vval = vsm[cur][colIdx];
        const float* kc = &ksm[cur][kseg*32];
        const float* qc = &qsm[cur][kseg*32];

        float r0=0.f, r1=0.f, r2=0.f, r3=0.f;
        #pragma unroll
        for (int i = 0; i < 32; i += 4) {
            float4 k4 = *(const float4*)(kc + i);
            r0 = fmaf(St[i],   k4.x, r0);
            r1 = fmaf(St[i+1], k4.y, r1);
            r2 = fmaf(St[i+2], k4.z, r2);
            r3 = fmaf(St[i+3], k4.w, r3);
        }
        redr[tid] = (r0 + r1) + (r2 + r3);
        __syncthreads();
        float rs  = redr[colIdx] + redr[colIdx+32] + redr[colIdx+64] + redr[colIdx+96];
        float err = vval - gv*rs;
        float w   = bv*err;

        float o0=0.f, o1=0.f, o2=0.f, o3=0.f;
        #pragma unroll
        for (int i = 0; i < 32; i += 4) {
            float4 k4 = *(const float4*)(kc + i);
            float4 q4 = *(const float4*)(qc + i);
            St[i]   = fmaf(gv, St[i],   k4.x*w); o0 = fmaf(St[i],   q4.x, o0);
            St[i+1] = fmaf(gv, St[i+1], k4.y*w); o1 = fmaf(St[i+1], q4.y, o1);
            St[i+2] = fmaf(gv, St[i+2], k4.z*w); o2 = fmaf(St[i+2], q4.z, o2);
            St[i+3] = fmaf(gv, St[i+3], k4.w*w); o3 = fmaf(St[i+3], q4.w, o3);
        }
        redo[tid] = (o0 + o1) + (o2 + o3);

        if (t + 1 < SS) {
            ksm[nxt][tid] = knr;
            qsm[nxt][tid] = qnr;
            if (tid < 32) vsm[nxt][tid] = vnr;
            if (tid == 0) { gsm[nxt] = gnr; bsm[nxt] = bnr; }
        }
        __syncthreads();
        if (kseg == 0) {
            float os = redo[colIdx] + redo[colIdx+32] + redo[colIdx+64] + redo[colIdx+96];
            op[(size_t)t*VD + colIdx] = os;
        }
    }
}

// ---------------- RMSNorm + gate (silu(x@Wg.T)), emits tf32 bits ---------
__global__ void rmsnorm_gate_kernel(const float* __restrict__ norm_w)
{
    int row = blockIdx.x;
    int tid = threadIdx.x;   // 256
    float vals[8];
    float ss = 0.f;
    #pragma unroll
    for (int i = 0; i < 8; i++) {
        float v = g_o[(size_t)row*VD + i*256 + tid];
        vals[i] = v;
        ss += v*v;
    }
    #pragma unroll
    for (int o = 16; o; o >>= 1) ss += __shfl_xor_sync(0xffffffffu, ss, o);
    __shared__ float sred[8];
    if ((tid & 31) == 0) sred[tid >> 5] = ss;
    __syncthreads();
    float tot = 0.f;
    #pragma unroll
    for (int i = 0; i < 8; i++) tot += sred[i];
    float scale = rsqrtf(tot * (1.f/VD) + 1e-6f);
    #pragma unroll
    for (int i = 0; i < 8; i++) {
        int c = i*256 + tid;
        float gl = g_glin[(size_t)row*VD + c];
        float r  = vals[i] * scale * norm_w[c] * (gl / (1.f + expf(-gl)));
        g_ogt[(size_t)row*VD + c] = f2tf32(r);
    }
}

// ---------------- launch ----------------
// Fork/join: side stream runs ab + cvt(Wo); the glin GEMM is gated on an
// event AFTER conv so it executes inside rec_kernel's idle window.
extern "C" void kernel_launch(void* const* d_in, const int* in_sizes, int n_in,
                              void* d_out, int out_size)
{
    const float* x       = (const float*)d_in[0];
    const float* Wq      = (const float*)d_in[1];
    const float* Wk      = (const float*)d_in[2];
    const float* Wv      = (const float*)d_in[3];
    const float* Wa      = (const float*)d_in[4];
    const float* Wb      = (const float*)d_in[5];
    const float* Wg      = (const float*)d_in[6];
    const float* Wo      = (const float*)d_in[7];
    const float* cw_q    = (const float*)d_in[8];
    const float* cb_q    = (const float*)d_in[9];
    const float* cw_k    = (const float*)d_in[10];
    const float* cb_k    = (const float*)d_in[11];
    const float* cw_v    = (const float*)d_in[12];
    const float* cb_v    = (const float*)d_in[13];
    const float* A_log   = (const float*)d_in[14];
    const float* dt_bias = (const float*)d_in[15];
    const float* norm_w  = (const float*)d_in[16];

    float *qlin, *klin, *vlin, *glin, *qn, *kn, *vc;
    uint32_t *xt, *w4, *wot, *ogt;
    cudaGetSymbolAddress((void**)&qlin, g_qlin);
    cudaGetSymbolAddress((void**)&klin, g_klin);
    cudaGetSymbolAddress((void**)&vlin, g_vlin);
    cudaGetSymbolAddress((void**)&glin, g_glin);
    cudaGetSymbolAddress((void**)&qn,   g_qn);
    cudaGetSymbolAddress((void**)&kn,   g_kn);
    cudaGetSymbolAddress((void**)&vc,   g_vc);
    cudaGetSymbolAddress((void**)&xt,   g_xt);
    cudaGetSymbolAddress((void**)&w4,   g_w4);
    cudaGetSymbolAddress((void**)&wot,  g_wot);
    cudaGetSymbolAddress((void**)&ogt,  g_ogt);

    static int inited = 0;
    static cudaStream_t s2;
    static cudaEvent_t  evFork, evConv, evSide;
    if (!inited) {
        cudaFuncSetAttribute(mma_gemm_tf32,
                             cudaFuncAttributeMaxDynamicSharedMemorySize,
                             4*STAGE_WORDS*4);
        cudaFuncSetAttribute(ab_kernel,
                             cudaFuncAttributeMaxDynamicSharedMemorySize,
                             8*DIMV*4);
        cudaStreamCreateWithFlags(&s2, cudaStreamNonBlocking);
        cudaEventCreateWithFlags(&evFork, cudaEventDisableTiming);
        cudaEventCreateWithFlags(&evConv, cudaEventDisableTiming);
        cudaEventCreateWithFlags(&evSide, cudaEventDisableTiming);
        inited = 1;
    }
    size_t gemm_smem = 4*STAGE_WORDS*4;   // 73728 B

    // ---- fork: side stream starts with input-only work
    cudaEventRecord(evFork, 0);
    cudaStreamWaitEvent(s2, evFork, 0);
    ab_kernel<<<BS/8, 256, 8*DIMV*4, s2>>>(x, Wa, Wb, A_log, dt_bias);
    cvt_tf32_kernel<<<(DIMV*VD)/1024, 256, 0, s2>>>(Wo, wot);

    // ---- main stream: tf32 conversions (x + all 4 projection weights)
    cvt_tf32_kernel<<<(BS*DIMV)/1024, 256>>>(x, xt);
    CvtPtrs cp;
    cp.src[0]=Wq; cp.dst[0]=w4 + 0*(size_t)KD*DIMV;
    cp.src[1]=Wk; cp.dst[1]=w4 + 1*(size_t)KD*DIMV;
    cp.src[2]=Wv; cp.dst[2]=w4 + 2*(size_t)KD*DIMV;
    cp.src[3]=Wg; cp.dst[3]=w4 + 3*(size_t)KD*DIMV;
    cvt_w_kernel<<<dim3((KD*DIMV)/1024, 4), 256>>>(cp);

    // ---- main stream: q/k/v projection GEMM (grid.x=48 -> buf 0..2)
    GemmPtrs P;
    P.Bw[0] = w4 + 0*(size_t)KD*DIMV; P.C[0] = qlin;
    P.Bw[1] = w4 + 1*(size_t)KD*DIMV; P.C[1] = klin;
    P.Bw[2] = w4 + 2*(size_t)KD*DIMV; P.C[2] = vlin;
    P.Bw[3] = P.Bw[0];                P.C[3] = qlin;   // unused (grid.x=48)
    mma_gemm_tf32<<<dim3(48, 32), 256, gemm_smem>>>(xt, P, DIMV, KD);

    ConvPtrs cvp;
    cvp.in[0]=qlin; cvp.out[0]=qn; cvp.cw[0]=cw_q; cvp.cb[0]=cb_q;
    cvp.in[1]=klin; cvp.out[1]=kn; cvp.cw[1]=cw_k; cvp.cb[1]=cb_k;
    cvp.in[2]=vlin; cvp.out[2]=vc; cvp.cw[2]=cw_v; cvp.cb[2]=cb_v;
    conv_kernel<<<dim3(BS, H, 3), 128>>>(cvp);
    cudaEventRecord(evConv, 0);

    // side stream: glin GEMM gated on conv completion -> runs during rec
    cudaStreamWaitEvent(s2, evConv, 0);
    GemmPtrs Pg;
    Pg.Bw[0] = w4 + 3*(size_t)KD*DIMV; Pg.C[0] = glin;
    Pg.Bw[1] = Pg.Bw[0]; Pg.C[1] = glin;
    Pg.Bw[2] = Pg.Bw[0]; Pg.C[2] = glin;
    Pg.Bw[3] = Pg.Bw[0]; Pg.C[3] = glin;
    mma_gemm_tf32<<<dim3(16, 32), 256, gemm_smem, s2>>>(xt, Pg, DIMV, KD);
    cudaEventRecord(evSide, s2);

    rec_kernel<<<BB*H*4, 128>>>();

    // ---- join: rmsnorm needs glin (+ wot later)
    cudaStreamWaitEvent(0, evSide, 0);

    rmsnorm_gate_kernel<<<BS, 256>>>(norm_w);

    // output GEMM
    GemmPtrs Po;
    for (int i = 0; i < 4; i++) { Po.Bw[i] = wot; Po.C[i] = (float*)d_out; }
    mma_gemm_tf32<<<dim3(16, 32), 256, gemm_smem>>>(ogt, Po, VD, DIMV);
}